// round 1
// baseline (speedup 1.0000x reference)
#include <cuda_runtime.h>

// YOLOv1 loss, fused single-pass reduction.
// S=7, B=2, C=20, D=30, CELL=64, IMG=448, LAMBDA_COORD=5, LAMBDA_NOOBJ=0.5

#define D_FEAT 30
#define S_GRID 7
#define GBOX 8

__global__ void init_out(float* out) { out[0] = 0.0f; }

__global__ void __launch_bounds__(256) yolo_loss_kernel(
    const float* __restrict__ feat,
    const float* __restrict__ bboxes,
    const int*   __restrict__ labels,
    float* __restrict__ out,
    int N)
{
    const float CELL = 64.0f;
    const float INV_CELL = 1.0f / 64.0f;
    const float IMG = 448.0f;
    const float INV_IMG = 1.0f / 448.0f;

    float acc = 0.0f;

    const int tid = blockIdx.x * blockDim.x + threadIdx.x;
    const int nth = gridDim.x * blockDim.x;

    // ---- Part 1: noobj base term: 0.5 * sum over all cells of (c0^2 + c1^2)
    const long long cells = (long long)N * (S_GRID * S_GRID);
    for (long long i = tid; i < cells; i += nth) {
        const float* p = feat + i * D_FEAT;
        float c0 = __ldg(p + 4);
        float c1 = __ldg(p + 9);
        acc = fmaf(0.5f * c0, c0, acc);
        acc = fmaf(0.5f * c1, c1, acc);
    }

    // ---- Part 2: per (n, g) terms
    const int M = N * GBOX;
    for (int i = tid; i < M; i += nth) {
        const int n = i >> 3;
        const float4 bb = __ldg((const float4*)(bboxes + (size_t)i * 4));
        const float x1 = bb.x, y1 = bb.y, x2 = bb.z, y2 = bb.w;

        const float cx = 0.5f * (x1 + x2);
        const float cy = 0.5f * (y1 + y2);
        const float gw = x2 - x1;
        const float gh = y2 - y1;

        int col = (int)floorf(cx * INV_CELL);
        int row = (int)floorf(cy * INV_CELL);
        col = min(S_GRID - 1, max(0, col));
        row = min(S_GRID - 1, max(0, row));

        const float* cell = feat + ((size_t)n * (S_GRID * S_GRID) + row * S_GRID + col) * D_FEAT;

        const float gx0 = (float)col * CELL;
        const float gy0 = (float)row * CELL;
        const float tx = cx * INV_CELL - (float)col;
        const float ty = cy * INV_CELL - (float)row;
        const float stw = sqrtf(gw * INV_IMG);
        const float sth = sqrtf(gh * INV_IMG);
        const float a2 = fmaxf(x2 - x1, 0.0f) * fmaxf(y2 - y1, 0.0f);

        float px[2], py[2], pw[2], ph[2], pc[2], iou[2];
        #pragma unroll
        for (int b = 0; b < 2; b++) {
            px[b] = __ldg(cell + b * 5 + 0);
            py[b] = __ldg(cell + b * 5 + 1);
            pw[b] = __ldg(cell + b * 5 + 2);
            ph[b] = __ldg(cell + b * 5 + 3);
            pc[b] = __ldg(cell + b * 5 + 4);

            const float pcx = gx0 + px[b] * CELL;
            const float pcy = gy0 + py[b] * CELL;
            const float pwa = pw[b] * IMG;
            const float pha = ph[b] * IMG;
            const float bx1 = pcx - 0.5f * pwa;
            const float by1 = pcy - 0.5f * pha;
            const float bx2 = pcx + 0.5f * pwa;
            const float by2 = pcy + 0.5f * pha;

            const float ix1 = fmaxf(bx1, x1);
            const float iy1 = fmaxf(by1, y1);
            const float ix2 = fminf(bx2, x2);
            const float iy2 = fminf(by2, y2);
            const float inter = fmaxf(ix2 - ix1, 0.0f) * fmaxf(iy2 - iy1, 0.0f);
            const float a1 = fmaxf(bx2 - bx1, 0.0f) * fmaxf(by2 - by1, 0.0f);
            iou[b] = inter / (a1 + a2 - inter + 1e-6f);
        }

        // argmax over 2 boxes; first wins ties (jnp.argmax semantics)
        const int bi = (iou[1] > iou[0]) ? 1 : 0;

        // coord loss (LAMBDA_COORD = 5)
        const float dpx = px[bi] - tx;
        const float dpy = py[bi] - ty;
        const float dsw = sqrtf(fmaxf(pw[bi], 0.0f)) - stw;
        const float dsh = sqrtf(fmaxf(ph[bi], 0.0f)) - sth;
        acc += 5.0f * (dpx * dpx + dpy * dpy + dsw * dsw + dsh * dsh);

        // conf_obj
        const float dc = pc[bi] - iou[bi];
        acc = fmaf(dc, dc, acc);

        // noobj correction: subtract 0.5 * resp * pc^2
        acc = fmaf(-0.5f * pc[bi], pc[bi], acc);

        // class loss: sum(clsp^2) - 2*clsp[label] + 1
        const int lab = __ldg(labels + i);
        float cls = 1.0f;
        #pragma unroll
        for (int c = 0; c < 20; c++) {
            const float v = __ldg(cell + 10 + c);
            cls = fmaf(v, v, cls);
        }
        cls -= 2.0f * __ldg(cell + 10 + lab);
        acc += cls;
    }

    // ---- Block reduction, then one atomicAdd per block
    __shared__ float sm[8];
    const int lane = threadIdx.x & 31;
    const int wid = threadIdx.x >> 5;
    #pragma unroll
    for (int off = 16; off > 0; off >>= 1)
        acc += __shfl_down_sync(0xFFFFFFFFu, acc, off);
    if (lane == 0) sm[wid] = acc;
    __syncthreads();
    if (wid == 0) {
        float v = (lane < (blockDim.x >> 5)) ? sm[lane] : 0.0f;
        #pragma unroll
        for (int off = 4; off > 0; off >>= 1)
            v += __shfl_down_sync(0xFFFFFFFFu, v, off);
        if (lane == 0) atomicAdd(out, v);
    }
}

extern "C" void kernel_launch(void* const* d_in, const int* in_sizes, int n_in,
                              void* d_out, int out_size) {
    const float* feat   = (const float*)d_in[0];
    const float* bboxes = (const float*)d_in[1];
    const int*   labels = (const int*)d_in[2];
    float* out = (float*)d_out;

    const int N = in_sizes[0] / (S_GRID * S_GRID * D_FEAT);  // 16384

    init_out<<<1, 1>>>(out);

    const int threads = 256;
    const long long cells = (long long)N * (S_GRID * S_GRID);  // 802816
    const int blocks = (int)((cells + threads - 1) / threads); // 3136
    yolo_loss_kernel<<<blocks, threads>>>(feat, bboxes, labels, out, N);
}